// round 1
// baseline (speedup 1.0000x reference)
#include <cuda_runtime.h>
#include <cuda_bf16.h>
#include <math.h>

#define CC   8
#define NN   16384
#define DD   1024
#define DQQ  128
#define KK   128
#define CAND_CAP 2048

static __device__ __align__(16) float g_w[CC * DD];
static __device__ float g_cc[CC];
static __device__ float g_scores[CC * NN];
static __device__ int   g_topidx[CC * KK];
static __device__ float g_weights[CC * KK];
static __device__ float g_u[CC * DD];

__device__ __forceinline__ unsigned int f2k(float f) {
    unsigned int u = __float_as_uint(f);
    return (u & 0x80000000u) ? ~u : (u | 0x80000000u);
}
__device__ __forceinline__ float k2f(unsigned int k) {
    unsigned int u = (k & 0x80000000u) ? (k & 0x7fffffffu) : ~k;
    return __uint_as_float(u);
}

// ---------------------------------------------------------------------------
// Kernel A: per-cluster w_c = Wq @ (key_c @ Wq + bq),  c_c = bq . qk_c
// grid: (C), block: 128
// ---------------------------------------------------------------------------
__global__ void prep_kernel(const float* __restrict__ key_feats,
                            const float* __restrict__ Wq,
                            const float* __restrict__ bq) {
    __shared__ float s_key[DD];
    __shared__ float s_qk[DQQ];
    int c = blockIdx.x;
    int t = threadIdx.x;

    for (int i = t; i < DD; i += 128) s_key[i] = key_feats[c * DD + i];
    __syncthreads();

    // qk[t] = sum_i key[i] * Wq[i][t] + bq[t]   (coalesced over t)
    float s = bq[t];
    #pragma unroll 4
    for (int i = 0; i < DD; ++i) s += s_key[i] * Wq[i * DQQ + t];
    s_qk[t] = s;
    __syncthreads();

    // w[i] = sum_j Wq[i][j] * qk[j]
    for (int i = t; i < DD; i += 128) {
        const float* row = Wq + (size_t)i * DQQ;
        float acc = 0.f;
        #pragma unroll 8
        for (int j = 0; j < DQQ; ++j) acc += row[j] * s_qk[j];
        g_w[c * DD + i] = acc;
    }
    if (t == 0) {
        float cc = 0.f;
        for (int j = 0; j < DQQ; ++j) cc += bq[j] * s_qk[j];
        g_cc[c] = cc;
    }
}

// ---------------------------------------------------------------------------
// Kernel B: raw attention scores. warp-per-patch GEMV. THE 512MB kernel.
// grid: (128 tiles, C), block: 256 (8 warps), each warp does 16 patches
// ---------------------------------------------------------------------------
__global__ void __launch_bounds__(256) score_kernel(const float* __restrict__ feats) {
    const int c    = blockIdx.y;
    const int warp = threadIdx.x >> 5;
    const int lane = threadIdx.x & 31;

    // preload this lane's slice of w_c (8 float4 = 32 floats)
    float4 wreg[8];
    const float4* w4 = reinterpret_cast<const float4*>(g_w + c * DD);
    #pragma unroll
    for (int j = 0; j < 8; ++j) wreg[j] = w4[j * 32 + lane];
    const float cc = g_cc[c];

    const int PPB  = NN / 128;             // 128 patches per block
    const int base = blockIdx.x * PPB;

    for (int p = warp; p < PPB; p += 8) {
        const int n = base + p;
        const float4* row = reinterpret_cast<const float4*>(
            feats + ((size_t)c * NN + n) * DD);
        float acc = 0.f;
        #pragma unroll
        for (int j = 0; j < 8; ++j) {
            float4 f = row[j * 32 + lane];
            float4 w = wreg[j];
            acc += f.x * w.x + f.y * w.y + f.z * w.z + f.w * w.w;
        }
        #pragma unroll
        for (int o = 16; o > 0; o >>= 1)
            acc += __shfl_xor_sync(0xffffffffu, acc, o);
        if (lane == 0) g_scores[c * NN + n] = acc + cc;
    }
}

// ---------------------------------------------------------------------------
// Kernel C: per-cluster top-K (sorted desc, stable ties) + both softmaxes
// grid: (C), block: 1024
// ---------------------------------------------------------------------------
__device__ __forceinline__ unsigned int blk_sum_u32(unsigned int v, unsigned int* red) {
    int t = threadIdx.x;
    red[t] = v; __syncthreads();
    for (int s = 512; s > 0; s >>= 1) {
        if (t < s) red[t] += red[t + s];
        __syncthreads();
    }
    unsigned int r = red[0];
    __syncthreads();
    return r;
}
__device__ __forceinline__ unsigned int blk_max_u32(unsigned int v, unsigned int* red) {
    int t = threadIdx.x;
    red[t] = v; __syncthreads();
    for (int s = 512; s > 0; s >>= 1) {
        if (t < s) { unsigned int o = red[t + s]; if (o > red[t]) red[t] = o; }
        __syncthreads();
    }
    unsigned int r = red[0];
    __syncthreads();
    return r;
}
__device__ __forceinline__ float blk_sum_f32(float v, float* red) {
    int t = threadIdx.x;
    red[t] = v; __syncthreads();
    for (int s = 512; s > 0; s >>= 1) {
        if (t < s) red[t] += red[t + s];
        __syncthreads();
    }
    float r = red[0];
    __syncthreads();
    return r;
}

__global__ void __launch_bounds__(1024) select_kernel() {
    __shared__ unsigned int       hist[2048];
    __shared__ unsigned long long cand[CAND_CAP];
    __shared__ unsigned int       redu[1024];
    __shared__ float              redf[1024];
    __shared__ unsigned long long red64[1024];
    __shared__ unsigned int       s_cnt;
    __shared__ float              s_maxf, s_sum, s_p0;
    __shared__ unsigned long long s_prev;
    __shared__ float              pbuf[KK];

    const int c = blockIdx.x;
    const int t = threadIdx.x;
    const float invSqDQ = 0.08838834764831843f;  // 1/sqrt(128)
    const float invSqD  = 0.03125f;              // 1/sqrt(1024)

    hist[t] = 0u; hist[t + 1024] = 0u;
    if (t == 0) s_cnt = 0u;
    __syncthreads();

    // Pass 1: histogram of order-preserving keys + max
    unsigned int maxKey = 0u;
    for (int i = t; i < NN; i += 1024) {
        unsigned int key = f2k(g_scores[c * NN + i]);
        atomicAdd(&hist[key >> 21], 1u);
        if (key > maxKey) maxKey = key;
    }
    maxKey = blk_max_u32(maxKey, redu);
    if (t == 0) s_maxf = k2f(maxKey);
    __syncthreads();
    const float maxf = s_maxf;

    // Binary search for largest bucket B with count_ge(B) >= K
    int lo = 0, hi = 2047;
    while (lo < hi) {
        int mid = (lo + hi + 1) >> 1;
        unsigned int part = 0u;
        if (t >= mid) part += hist[t];
        part += hist[t + 1024];  // t+1024 >= 1024 > any reachable mid? no: mid can exceed 1024
        if (t + 1024 < mid) part -= hist[t + 1024];
        unsigned int cnt = blk_sum_u32(part, redu);
        if (cnt >= KK) lo = mid; else hi = mid - 1;
    }
    const int B = lo;

    // Pass 2: sum of exp (full softmax denominator) + candidate collection
    float esum = 0.f;
    for (int i = t; i < NN; i += 1024) {
        float f = g_scores[c * NN + i];
        esum += expf((f - maxf) * invSqDQ);
        unsigned int key = f2k(f);
        if ((int)(key >> 21) >= B) {
            unsigned int pos = atomicAdd(&s_cnt, 1u);
            if (pos < CAND_CAP)
                cand[pos] = ((unsigned long long)key << 14) |
                            (unsigned long long)(16383 - i);  // tie: lower idx wins
        }
    }
    esum = blk_sum_f32(esum, redf);
    if (t == 0) s_sum = esum;
    __syncthreads();
    const unsigned int M = s_cnt;

    if (M <= CAND_CAP) {
        // pad to power of two and bitonic sort descending
        int P = 128;
        while (P < (int)M) P <<= 1;
        for (int i = (int)M + t; i < P; i += 1024) cand[i] = 0ull;
        __syncthreads();
        for (int k = 2; k <= P; k <<= 1) {
            for (int j = k >> 1; j > 0; j >>= 1) {
                for (int i = t; i < P; i += 1024) {
                    int ixj = i ^ j;
                    if (ixj > i) {
                        unsigned long long a = cand[i], b = cand[ixj];
                        bool swap_ = ((i & k) == 0) ? (a < b) : (a > b);
                        if (swap_) { cand[i] = b; cand[ixj] = a; }
                    }
                }
                __syncthreads();
            }
        }
    } else {
        // Degenerate-ties fallback: K sequential arg-maxes (exact, slow, never hit
        // on continuous data)
        if (t == 0) s_prev = 0xFFFFFFFFFFFFFFFFull;
        __syncthreads();
        for (int kk = 0; kk < KK; ++kk) {
            unsigned long long prev = s_prev;
            unsigned long long local = 0ull;
            for (int i = t; i < NN; i += 1024) {
                unsigned int key = f2k(g_scores[c * NN + i]);
                unsigned long long v = ((unsigned long long)key << 14) |
                                       (unsigned long long)(16383 - i);
                if (v < prev && v > local) local = v;
            }
            red64[t] = local; __syncthreads();
            for (int s = 512; s > 0; s >>= 1) {
                if (t < s) { unsigned long long o = red64[t + s]; if (o > red64[t]) red64[t] = o; }
                __syncthreads();
            }
            if (t == 0) { cand[kk] = red64[0]; s_prev = red64[0]; }
            __syncthreads();
        }
    }

    // Top-128: first softmax probs, then re-softmax over top-K
    float p = 0.f;
    if (t < KK) {
        unsigned long long v = cand[t];
        int idx = 16383 - (int)(v & 0x3FFFull);
        unsigned int key = (unsigned int)(v >> 14);
        float f = k2f(key);
        p = expf((f - maxf) * invSqDQ) / s_sum;
        g_topidx[c * KK + t] = idx;
        pbuf[t] = p;
    }
    __syncthreads();
    if (t == 0) s_p0 = pbuf[0];  // largest prob (sorted desc)
    __syncthreads();
    float e = (t < KK) ? expf((p - s_p0) * invSqD) : 0.f;
    float wsum = blk_sum_f32(e, redf);
    if (t < KK) g_weights[c * KK + t] = e / wsum;
}

// ---------------------------------------------------------------------------
// Kernel D: gather selected rows to output + weighted sum u_c
// grid: (C, 8), block: 128. Each block owns a 128-column segment.
// ---------------------------------------------------------------------------
__global__ void __launch_bounds__(128) gather_kernel(const float* __restrict__ feats,
                                                     float* __restrict__ out) {
    __shared__ float sw[KK];
    __shared__ int   sidx[KK];
    const int c = blockIdx.x;
    const int t = threadIdx.x;
    sw[t]   = g_weights[c * KK + t];
    sidx[t] = g_topidx[c * KK + t];
    __syncthreads();

    const int col = blockIdx.y * 128 + t;
    float acc = 0.f;
    #pragma unroll 4
    for (int k = 0; k < KK; ++k) {
        float v = feats[((size_t)c * NN + sidx[k]) * DD + col];
        out[((size_t)(c * KK + k)) * DD + col] = v;
        acc += sw[k] * v;
    }
    g_u[c * DD + col] = acc;
}

// ---------------------------------------------------------------------------
// Kernel E: fusion_c = u_c @ Wv + bv
// grid: (C, 8), block: 128
// ---------------------------------------------------------------------------
__global__ void __launch_bounds__(128) fusion_kernel(const float* __restrict__ Wv,
                                                     const float* __restrict__ bv,
                                                     float* __restrict__ out) {
    __shared__ float su[DD];
    const int c = blockIdx.x;
    const int t = threadIdx.x;
    for (int i = t; i < DD; i += 128) su[i] = g_u[c * DD + i];
    __syncthreads();

    const int j = blockIdx.y * 128 + t;
    float acc = bv[j];
    #pragma unroll 8
    for (int i = 0; i < DD; ++i) acc += su[i] * Wv[(size_t)i * DD + j];
    out[(size_t)CC * KK * DD + (size_t)c * DD + j] = acc;
}

// ---------------------------------------------------------------------------
extern "C" void kernel_launch(void* const* d_in, const int* in_sizes, int n_in,
                              void* d_out, int out_size) {
    const float* feats = (const float*)d_in[0];  // [C, N, D]
    const float* keyf  = (const float*)d_in[1];  // [C, 1, D]
    const float* Wq    = (const float*)d_in[2];  // [D, DQ]
    const float* bq    = (const float*)d_in[3];  // [DQ]
    const float* Wv    = (const float*)d_in[4];  // [D, D]
    const float* bv    = (const float*)d_in[5];  // [D]
    float* out = (float*)d_out;                  // [C*K*D | C*D]

    prep_kernel<<<CC, 128>>>(keyf, Wq, bq);
    score_kernel<<<dim3(128, CC), 256>>>(feats);
    select_kernel<<<CC, 1024>>>();
    gather_kernel<<<dim3(CC, 8), 128>>>(feats, out);
    fusion_kernel<<<dim3(CC, 8), 128>>>(Wv, bv, out);
}

// round 3
// speedup vs baseline: 1.1907x; 1.1907x over previous
#include <cuda_runtime.h>
#include <cuda_bf16.h>
#include <math.h>

#define CC   8
#define NN   16384
#define DD   1024
#define DQQ  128
#define KK   128
#define CAND_CAP 2048

static __device__ __align__(16) float g_w[CC * DD];
static __device__ float g_cc[CC];
static __device__ float g_scores[CC * NN];
static __device__ int   g_topidx[CC * KK];
static __device__ float g_weights[CC * KK];
static __device__ float g_u[CC * DD];

__device__ __forceinline__ unsigned int f2k(float f) {
    unsigned int u = __float_as_uint(f);
    return (u & 0x80000000u) ? ~u : (u | 0x80000000u);
}
__device__ __forceinline__ float k2f(unsigned int k) {
    unsigned int u = (k & 0x80000000u) ? (k & 0x7fffffffu) : ~k;
    return __uint_as_float(u);
}

// ---------------------------------------------------------------------------
// Kernel A: per-cluster w_c = Wq @ (key_c @ Wq + bq),  c_c = bq . qk_c
// Also: zero g_u, init fusion output region to bv (required per graph replay).
// grid: (C), block: 128
// ---------------------------------------------------------------------------
__global__ void prep_kernel(const float* __restrict__ key_feats,
                            const float* __restrict__ Wq,
                            const float* __restrict__ bq,
                            const float* __restrict__ bv,
                            float* __restrict__ out) {
    __shared__ float s_key[DD];
    __shared__ float s_qk[DQQ];
    int c = blockIdx.x;
    int t = threadIdx.x;

    for (int i = t; i < DD; i += 128) {
        s_key[i] = key_feats[c * DD + i];
        g_u[c * DD + i] = 0.f;
        out[(size_t)CC * KK * DD + (size_t)c * DD + i] = bv[i];
    }
    __syncthreads();

    // qk[t] = sum_i key[i] * Wq[i][t] + bq[t]   (coalesced over t)
    float s = bq[t];
    #pragma unroll 4
    for (int i = 0; i < DD; ++i) s += s_key[i] * Wq[i * DQQ + t];
    s_qk[t] = s;
    __syncthreads();

    // w[i] = sum_j Wq[i][j] * qk[j]
    for (int i = t; i < DD; i += 128) {
        const float* row = Wq + (size_t)i * DQQ;
        float acc = 0.f;
        #pragma unroll 8
        for (int j = 0; j < DQQ; ++j) acc += row[j] * s_qk[j];
        g_w[c * DD + i] = acc;
    }
    if (t == 0) {
        float cc = 0.f;
        for (int j = 0; j < DQQ; ++j) cc += bq[j] * s_qk[j];
        g_cc[c] = cc;
    }
}

// ---------------------------------------------------------------------------
// Kernel B: raw attention scores. Warp processes 2 rows per iteration with all
// 16 float4 loads in flight before consumption. THE 512MB kernel.
// grid: (256, C), block: 256 (8 warps). 64 patches per block.
// ---------------------------------------------------------------------------
__global__ void __launch_bounds__(256) score_kernel(const float* __restrict__ feats) {
    const int c    = blockIdx.y;
    const int warp = threadIdx.x >> 5;
    const int lane = threadIdx.x & 31;

    // preload this lane's slice of w_c (8 float4 = 32 floats)
    float4 wreg[8];
    const float4* w4 = reinterpret_cast<const float4*>(g_w + c * DD);
    #pragma unroll
    for (int j = 0; j < 8; ++j) wreg[j] = w4[j * 32 + lane];
    const float cc = g_cc[c];

    const int PPB  = 64;                   // patches per block
    const int base = blockIdx.x * PPB;

    #pragma unroll
    for (int p = warp * 2; p < PPB; p += 16) {
        const int n0 = base + p;
        const float4* r0 = reinterpret_cast<const float4*>(
            feats + ((size_t)c * NN + n0) * DD);
        const float4* r1 = reinterpret_cast<const float4*>(
            feats + ((size_t)c * NN + n0 + 1) * DD);
        float4 a[8], b[8];
        #pragma unroll
        for (int j = 0; j < 8; ++j) a[j] = r0[j * 32 + lane];
        #pragma unroll
        for (int j = 0; j < 8; ++j) b[j] = r1[j * 32 + lane];

        float acc0 = 0.f, acc1 = 0.f;
        #pragma unroll
        for (int j = 0; j < 8; ++j) {
            float4 w = wreg[j];
            acc0 += a[j].x * w.x + a[j].y * w.y + a[j].z * w.z + a[j].w * w.w;
            acc1 += b[j].x * w.x + b[j].y * w.y + b[j].z * w.z + b[j].w * w.w;
        }
        #pragma unroll
        for (int o = 16; o > 0; o >>= 1) {
            acc0 += __shfl_xor_sync(0xffffffffu, acc0, o);
            acc1 += __shfl_xor_sync(0xffffffffu, acc1, o);
        }
        if (lane == 0) {
            g_scores[c * NN + n0]     = acc0 + cc;
            g_scores[c * NN + n0 + 1] = acc1 + cc;
        }
    }
}

// ---------------------------------------------------------------------------
// Kernel C: per-cluster top-K (sorted desc, stable ties) + both softmaxes.
// Single data pass (zero-reference exp is safe: |s|/sqrt(128) < ~3), suffix
// scan instead of binary search. grid: (C), block: 1024
// ---------------------------------------------------------------------------
__device__ __forceinline__ float blk_sum_f32(float v, float* red) {
    int t = threadIdx.x;
    red[t] = v; __syncthreads();
    for (int s = 512; s > 0; s >>= 1) {
        if (t < s) red[t] += red[t + s];
        __syncthreads();
    }
    float r = red[0];
    __syncthreads();
    return r;
}
__device__ __forceinline__ int blk_max_i32(int v, int* red) {
    int t = threadIdx.x;
    red[t] = v; __syncthreads();
    for (int s = 512; s > 0; s >>= 1) {
        if (t < s) { int o = red[t + s]; if (o > red[t]) red[t] = o; }
        __syncthreads();
    }
    int r = red[0];
    __syncthreads();
    return r;
}

__global__ void __launch_bounds__(1024) select_kernel() {
    __shared__ unsigned int       hist[2048];
    __shared__ unsigned long long cand[CAND_CAP];
    __shared__ float              redf[1024];
    __shared__ int                redi[1024];
    __shared__ unsigned long long red64[1024];
    __shared__ unsigned int       s_cnt;
    __shared__ float              s_sum, s_p0;
    __shared__ unsigned long long s_prev;

    const int c = blockIdx.x;
    const int t = threadIdx.x;
    const float invSqDQ = 0.08838834764831843f;  // 1/sqrt(128)
    const float invSqD  = 0.03125f;              // 1/sqrt(1024)

    hist[t] = 0u; hist[t + 1024] = 0u;
    if (t == 0) s_cnt = 0u;
    __syncthreads();

    // Pass 1: histogram of order-preserving keys + zero-reference exp sum
    float esum = 0.f;
    #pragma unroll
    for (int i = t; i < NN; i += 1024) {
        float f = g_scores[c * NN + i];
        esum += expf(f * invSqDQ);
        atomicAdd(&hist[f2k(f) >> 21], 1u);
    }
    esum = blk_sum_f32(esum, redf);
    if (t == 0) s_sum = esum;
    __syncthreads();

    // Suffix scan: hist[b] <- count of keys in buckets >= b (Hillis-Steele)
    #pragma unroll
    for (int s = 1; s < 2048; s <<= 1) {
        unsigned int a0 = hist[t]        + ((t + s < 2048)        ? hist[t + s]        : 0u);
        unsigned int a1 = hist[t + 1024] + ((t + 1024 + s < 2048) ? hist[t + 1024 + s] : 0u);
        __syncthreads();
        hist[t] = a0; hist[t + 1024] = a1;
        __syncthreads();
    }

    // B = largest bucket with suffix count >= K
    int loc = -1;
    if (hist[t + 1024] >= KK) loc = t + 1024;
    else if (hist[t] >= KK)   loc = t;
    const int B = blk_max_i32(loc, redi);
    __syncthreads();

    // Pass 2: collect candidates (L2-resident scores)
    for (int i = t; i < NN; i += 1024) {
        unsigned int key = f2k(g_scores[c * NN + i]);
        if ((int)(key >> 21) >= B) {
            unsigned int pos = atomicAdd(&s_cnt, 1u);
            if (pos < CAND_CAP)
                cand[pos] = ((unsigned long long)key << 14) |
                            (unsigned long long)(16383 - i);  // tie: lower idx wins
        }
    }
    __syncthreads();
    const unsigned int M = s_cnt;

    if (M <= CAND_CAP) {
        int P = 128;
        while (P < (int)M) P <<= 1;
        for (int i = (int)M + t; i < P; i += 1024) cand[i] = 0ull;
        __syncthreads();
        for (int k = 2; k <= P; k <<= 1) {
            for (int j = k >> 1; j > 0; j >>= 1) {
                for (int i = t; i < P; i += 1024) {
                    int ixj = i ^ j;
                    if (ixj > i) {
                        unsigned long long a = cand[i], b = cand[ixj];
                        bool swap_ = ((i & k) == 0) ? (a < b) : (a > b);
                        if (swap_) { cand[i] = b; cand[ixj] = a; }
                    }
                }
                __syncthreads();
            }
        }
    } else {
        // Degenerate-ties fallback: K sequential arg-maxes (exact, never hit on
        // continuous data)
        if (t == 0) s_prev = 0xFFFFFFFFFFFFFFFFull;
        __syncthreads();
        for (int kk = 0; kk < KK; ++kk) {
            unsigned long long prev = s_prev;
            unsigned long long local = 0ull;
            for (int i = t; i < NN; i += 1024) {
                unsigned int key = f2k(g_scores[c * NN + i]);
                unsigned long long v = ((unsigned long long)key << 14) |
                                       (unsigned long long)(16383 - i);
                if (v < prev && v > local) local = v;
            }
            red64[t] = local; __syncthreads();
            for (int s = 512; s > 0; s >>= 1) {
                if (t < s) { unsigned long long o = red64[t + s]; if (o > red64[t]) red64[t] = o; }
                __syncthreads();
            }
            if (t == 0) { cand[kk] = red64[0]; s_prev = red64[0]; }
            __syncthreads();
        }
    }

    // Top-128: first-softmax probs, then re-softmax over top-K
    float p = 0.f;
    if (t < KK) {
        unsigned long long v = cand[t];
        int idx = 16383 - (int)(v & 0x3FFFull);
        float f = k2f((unsigned int)(v >> 14));
        p = expf(f * invSqDQ) / s_sum;
        g_topidx[c * KK + t] = idx;
        if (t == 0) s_p0 = p;   // cand sorted desc -> t==0 is max prob
    }
    __syncthreads();
    float e = (t < KK) ? expf((p - s_p0) * invSqD) : 0.f;
    float wsum = blk_sum_f32(e, redf);
    if (t < KK) g_weights[c * KK + t] = e / wsum;
}

// ---------------------------------------------------------------------------
// Kernel D: gather selected rows to output + partial weighted sums into g_u.
// grid: (C, 32), block: 256 (thread = one float4 column; 4 rows per block)
// ---------------------------------------------------------------------------
__global__ void __launch_bounds__(256) gather_kernel(const float* __restrict__ feats,
                                                     float* __restrict__ out) {
    __shared__ float sw[4];
    __shared__ int   sidx[4];
    const int c  = blockIdx.x;
    const int ks = blockIdx.y * 4;
    const int t  = threadIdx.x;
    if (t < 4) {
        sw[t]   = g_weights[c * KK + ks + t];
        sidx[t] = g_topidx[c * KK + ks + t];
    }
    __syncthreads();

    float4 acc = make_float4(0.f, 0.f, 0.f, 0.f);
    #pragma unroll
    for (int r = 0; r < 4; ++r) {
        const float4* row = reinterpret_cast<const float4*>(
            feats + ((size_t)c * NN + sidx[r]) * DD);
        float4 v = row[t];
        reinterpret_cast<float4*>(out + ((size_t)(c * KK + ks + r)) * DD)[t] = v;
        float w = sw[r];
        acc.x += w * v.x; acc.y += w * v.y; acc.z += w * v.z; acc.w += w * v.w;
    }
    float* u = g_u + c * DD + t * 4;
    atomicAdd(u + 0, acc.x);
    atomicAdd(u + 1, acc.y);
    atomicAdd(u + 2, acc.z);
    atomicAdd(u + 3, acc.w);
}

// ---------------------------------------------------------------------------
// Kernel E: fusion_c += u_c @ Wv (bv pre-initialized by prep)
// grid: (C, 8 colsegs, 4 isegs), block: 128
// ---------------------------------------------------------------------------
__global__ void __launch_bounds__(128) fusion_kernel(const float* __restrict__ Wv,
                                                     float* __restrict__ out) {
    __shared__ float su[256];
    const int c  = blockIdx.x;
    const int t  = threadIdx.x;
    const int i0 = blockIdx.z * 256;
    su[t]       = g_u[c * DD + i0 + t];
    su[t + 128] = g_u[c * DD + i0 + t + 128];
    __syncthreads();

    const int j = blockIdx.y * 128 + t;
    float acc = 0.f;
    #pragma unroll 8
    for (int i = 0; i < 256; ++i) acc += su[i] * Wv[(size_t)(i0 + i) * DD + j];
    atomicAdd(&out[(size_t)CC * KK * DD + (size_t)c * DD + j], acc);
}

// ---------------------------------------------------------------------------
extern "C" void kernel_launch(void* const* d_in, const int* in_sizes, int n_in,
                              void* d_out, int out_size) {
    const float* feats = (const float*)d_in[0];  // [C, N, D]
    const float* keyf  = (const float*)d_in[1];  // [C, 1, D]
    const float* Wq    = (const float*)d_in[2];  // [D, DQ]
    const float* bq    = (const float*)d_in[3];  // [DQ]
    const float* Wv    = (const float*)d_in[4];  // [D, D]
    const float* bv    = (const float*)d_in[5];  // [D]
    float* out = (float*)d_out;                  // [C*K*D | C*D]

    prep_kernel<<<CC, 128>>>(keyf, Wq, bq, bv, out);
    score_kernel<<<dim3(256, CC), 256>>>(feats);
    select_kernel<<<CC, 1024>>>();
    gather_kernel<<<dim3(CC, 32), 256>>>(feats, out);
    fusion_kernel<<<dim3(CC, 8, 4), 128>>>(Wv, out);
}

// round 4
// speedup vs baseline: 1.2866x; 1.0806x over previous
#include <cuda_runtime.h>
#include <cuda_bf16.h>
#include <math.h>

#define CC   8
#define NN   16384
#define DD   1024
#define DQQ  128
#define KK   128
#define CAND_CAP 2048

static __device__ __align__(16) float g_w[CC * DD];
static __device__ float g_cc[CC];
static __device__ float g_scores[CC * NN];
static __device__ int   g_topidx[CC * KK];
static __device__ float g_weights[CC * KK];
static __device__ float g_u[CC * DD];

__device__ __forceinline__ unsigned int f2k(float f) {
    unsigned int u = __float_as_uint(f);
    return (u & 0x80000000u) ? ~u : (u | 0x80000000u);
}
__device__ __forceinline__ float k2f(unsigned int k) {
    unsigned int u = (k & 0x80000000u) ? (k & 0x7fffffffu) : ~k;
    return __uint_as_float(u);
}

// ---------------------------------------------------------------------------
// Kernel A: per-cluster w_c = Wq @ (key_c @ Wq + bq),  c_c = bq . qk_c
// Also: zero g_u, init fusion output region to bv (required per graph replay).
// grid: (C), block: 128
// ---------------------------------------------------------------------------
__global__ void prep_kernel(const float* __restrict__ key_feats,
                            const float* __restrict__ Wq,
                            const float* __restrict__ bq,
                            const float* __restrict__ bv,
                            float* __restrict__ out) {
    __shared__ float s_key[DD];
    __shared__ float s_qk[DQQ];
    int c = blockIdx.x;
    int t = threadIdx.x;

    for (int i = t; i < DD; i += 128) {
        s_key[i] = key_feats[c * DD + i];
        g_u[c * DD + i] = 0.f;
        out[(size_t)CC * KK * DD + (size_t)c * DD + i] = bv[i];
    }
    __syncthreads();

    // qk[t] = sum_i key[i] * Wq[i][t] + bq[t]   (coalesced over t)
    float s = bq[t];
    #pragma unroll 4
    for (int i = 0; i < DD; ++i) s += s_key[i] * Wq[i * DQQ + t];
    s_qk[t] = s;
    __syncthreads();

    // w[i] = sum_j Wq[i][j] * qk[j]
    for (int i = t; i < DD; i += 128) {
        const float* row = Wq + (size_t)i * DQQ;
        float acc = 0.f;
        #pragma unroll 8
        for (int j = 0; j < DQQ; ++j) acc += row[j] * s_qk[j];
        g_w[c * DD + i] = acc;
    }
    if (t == 0) {
        float cc = 0.f;
        for (int j = 0; j < DQQ; ++j) cc += bq[j] * s_qk[j];
        g_cc[c] = cc;
    }
}

// ---------------------------------------------------------------------------
// Kernel B: raw attention scores. Warp-per-row, ONE row per iteration, no
// outer unroll: only 8 float4 + wreg live -> ~80 regs, no spills, high
// occupancy supplies the MLP. THE 512MB kernel.
// grid: (256, C), block: 256 (8 warps). 64 patches per block, 8 per warp.
// ---------------------------------------------------------------------------
__global__ void __launch_bounds__(256) score_kernel(const float* __restrict__ feats) {
    const int c    = blockIdx.y;
    const int warp = threadIdx.x >> 5;
    const int lane = threadIdx.x & 31;

    // this lane's slice of w_c (8 float4 = 32 floats, held in registers)
    float4 wreg[8];
    const float4* w4 = reinterpret_cast<const float4*>(g_w + c * DD);
    #pragma unroll
    for (int j = 0; j < 8; ++j) wreg[j] = w4[j * 32 + lane];
    const float cc = g_cc[c];

    const int PPB  = 64;
    const int base = blockIdx.x * PPB;

    #pragma unroll 1
    for (int p = warp; p < PPB; p += 8) {
        const int n = base + p;
        const float4* row = reinterpret_cast<const float4*>(
            feats + ((size_t)c * NN + n) * DD);
        // 8 independent 16B loads issued before any consumption
        float4 f0 = row[0 * 32 + lane];
        float4 f1 = row[1 * 32 + lane];
        float4 f2 = row[2 * 32 + lane];
        float4 f3 = row[3 * 32 + lane];
        float4 f4 = row[4 * 32 + lane];
        float4 f5 = row[5 * 32 + lane];
        float4 f6 = row[6 * 32 + lane];
        float4 f7 = row[7 * 32 + lane];

        float acc = f0.x * wreg[0].x + f0.y * wreg[0].y + f0.z * wreg[0].z + f0.w * wreg[0].w;
        acc += f1.x * wreg[1].x + f1.y * wreg[1].y + f1.z * wreg[1].z + f1.w * wreg[1].w;
        acc += f2.x * wreg[2].x + f2.y * wreg[2].y + f2.z * wreg[2].z + f2.w * wreg[2].w;
        acc += f3.x * wreg[3].x + f3.y * wreg[3].y + f3.z * wreg[3].z + f3.w * wreg[3].w;
        acc += f4.x * wreg[4].x + f4.y * wreg[4].y + f4.z * wreg[4].z + f4.w * wreg[4].w;
        acc += f5.x * wreg[5].x + f5.y * wreg[5].y + f5.z * wreg[5].z + f5.w * wreg[5].w;
        acc += f6.x * wreg[6].x + f6.y * wreg[6].y + f6.z * wreg[6].z + f6.w * wreg[6].w;
        acc += f7.x * wreg[7].x + f7.y * wreg[7].y + f7.z * wreg[7].z + f7.w * wreg[7].w;

        #pragma unroll
        for (int o = 16; o > 0; o >>= 1)
            acc += __shfl_xor_sync(0xffffffffu, acc, o);
        if (lane == 0) g_scores[c * NN + n] = acc + cc;
    }
}

// ---------------------------------------------------------------------------
// Kernel C: per-cluster top-K (sorted desc, stable ties) + both softmaxes.
// grid: (C), block: 1024
// ---------------------------------------------------------------------------
__device__ __forceinline__ float blk_sum_f32(float v, float* red) {
    int t = threadIdx.x;
    red[t] = v; __syncthreads();
    for (int s = 512; s > 0; s >>= 1) {
        if (t < s) red[t] += red[t + s];
        __syncthreads();
    }
    float r = red[0];
    __syncthreads();
    return r;
}
__device__ __forceinline__ int blk_max_i32(int v, int* red) {
    int t = threadIdx.x;
    red[t] = v; __syncthreads();
    for (int s = 512; s > 0; s >>= 1) {
        if (t < s) { int o = red[t + s]; if (o > red[t]) red[t] = o; }
        __syncthreads();
    }
    int r = red[0];
    __syncthreads();
    return r;
}

__global__ void __launch_bounds__(1024) select_kernel() {
    __shared__ unsigned int       hist[2048];
    __shared__ unsigned long long cand[CAND_CAP];
    __shared__ float              redf[1024];
    __shared__ int                redi[1024];
    __shared__ unsigned long long red64[1024];
    __shared__ unsigned int       s_cnt;
    __shared__ float              s_sum, s_p0;
    __shared__ unsigned long long s_prev;

    const int c = blockIdx.x;
    const int t = threadIdx.x;
    const float invSqDQ = 0.08838834764831843f;  // 1/sqrt(128)
    const float invSqD  = 0.03125f;              // 1/sqrt(1024)

    hist[t] = 0u; hist[t + 1024] = 0u;
    if (t == 0) s_cnt = 0u;
    __syncthreads();

    // Pass 1: histogram of order-preserving keys + zero-reference exp sum
    // (scores bounded: |s|/sqrt(128) < ~3, no overflow without max-shift)
    float esum = 0.f;
    #pragma unroll
    for (int i = t; i < NN; i += 1024) {
        float f = g_scores[c * NN + i];
        esum += expf(f * invSqDQ);
        atomicAdd(&hist[f2k(f) >> 21], 1u);
    }
    esum = blk_sum_f32(esum, redf);
    if (t == 0) s_sum = esum;
    __syncthreads();

    // Suffix scan: hist[b] <- count of keys in buckets >= b (Hillis-Steele)
    #pragma unroll
    for (int s = 1; s < 2048; s <<= 1) {
        unsigned int a0 = hist[t]        + ((t + s < 2048)        ? hist[t + s]        : 0u);
        unsigned int a1 = hist[t + 1024] + ((t + 1024 + s < 2048) ? hist[t + 1024 + s] : 0u);
        __syncthreads();
        hist[t] = a0; hist[t + 1024] = a1;
        __syncthreads();
    }

    // B = largest bucket with suffix count >= K
    int loc = -1;
    if (hist[t + 1024] >= KK) loc = t + 1024;
    else if (hist[t] >= KK)   loc = t;
    const int B = blk_max_i32(loc, redi);
    __syncthreads();

    // Pass 2: collect candidates (L2-resident scores)
    for (int i = t; i < NN; i += 1024) {
        unsigned int key = f2k(g_scores[c * NN + i]);
        if ((int)(key >> 21) >= B) {
            unsigned int pos = atomicAdd(&s_cnt, 1u);
            if (pos < CAND_CAP)
                cand[pos] = ((unsigned long long)key << 14) |
                            (unsigned long long)(16383 - i);  // tie: lower idx wins
        }
    }
    __syncthreads();
    const unsigned int M = s_cnt;

    if (M <= CAND_CAP) {
        int P = 128;
        while (P < (int)M) P <<= 1;
        for (int i = (int)M + t; i < P; i += 1024) cand[i] = 0ull;
        __syncthreads();
        for (int k = 2; k <= P; k <<= 1) {
            for (int j = k >> 1; j > 0; j >>= 1) {
                for (int i = t; i < P; i += 1024) {
                    int ixj = i ^ j;
                    if (ixj > i) {
                        unsigned long long a = cand[i], b = cand[ixj];
                        bool swap_ = ((i & k) == 0) ? (a < b) : (a > b);
                        if (swap_) { cand[i] = b; cand[ixj] = a; }
                    }
                }
                __syncthreads();
            }
        }
    } else {
        // Degenerate-ties fallback: K sequential arg-maxes (exact, never hit on
        // continuous data)
        if (t == 0) s_prev = 0xFFFFFFFFFFFFFFFFull;
        __syncthreads();
        for (int kk = 0; kk < KK; ++kk) {
            unsigned long long prev = s_prev;
            unsigned long long local = 0ull;
            for (int i = t; i < NN; i += 1024) {
                unsigned int key = f2k(g_scores[c * NN + i]);
                unsigned long long v = ((unsigned long long)key << 14) |
                                       (unsigned long long)(16383 - i);
                if (v < prev && v > local) local = v;
            }
            red64[t] = local; __syncthreads();
            for (int s = 512; s > 0; s >>= 1) {
                if (t < s) { unsigned long long o = red64[t + s]; if (o > red64[t]) red64[t] = o; }
                __syncthreads();
            }
            if (t == 0) { cand[kk] = red64[0]; s_prev = red64[0]; }
            __syncthreads();
        }
    }

    // Top-128: first-softmax probs, then re-softmax over top-K
    float p = 0.f;
    if (t < KK) {
        unsigned long long v = cand[t];
        int idx = 16383 - (int)(v & 0x3FFFull);
        float f = k2f((unsigned int)(v >> 14));
        p = expf(f * invSqDQ) / s_sum;
        g_topidx[c * KK + t] = idx;
        if (t == 0) s_p0 = p;   // cand sorted desc -> t==0 is max prob
    }
    __syncthreads();
    float e = (t < KK) ? expf((p - s_p0) * invSqD) : 0.f;
    float wsum = blk_sum_f32(e, redf);
    if (t < KK) g_weights[c * KK + t] = e / wsum;
}

// ---------------------------------------------------------------------------
// Kernel D: gather selected rows to output + partial weighted sums into g_u.
// grid: (C, 32), block: 256 (thread = one float4 column; 4 rows per block)
// ---------------------------------------------------------------------------
__global__ void __launch_bounds__(256) gather_kernel(const float* __restrict__ feats,
                                                     float* __restrict__ out) {
    __shared__ float sw[4];
    __shared__ int   sidx[4];
    const int c  = blockIdx.x;
    const int ks = blockIdx.y * 4;
    const int t  = threadIdx.x;
    if (t < 4) {
        sw[t]   = g_weights[c * KK + ks + t];
        sidx[t] = g_topidx[c * KK + ks + t];
    }
    __syncthreads();

    float4 acc = make_float4(0.f, 0.f, 0.f, 0.f);
    #pragma unroll
    for (int r = 0; r < 4; ++r) {
        const float4* row = reinterpret_cast<const float4*>(
            feats + ((size_t)c * NN + sidx[r]) * DD);
        float4 v = row[t];
        reinterpret_cast<float4*>(out + ((size_t)(c * KK + ks + r)) * DD)[t] = v;
        float w = sw[r];
        acc.x += w * v.x; acc.y += w * v.y; acc.z += w * v.z; acc.w += w * v.w;
    }
    float* u = g_u + c * DD + t * 4;
    atomicAdd(u + 0, acc.x);
    atomicAdd(u + 1, acc.y);
    atomicAdd(u + 2, acc.z);
    atomicAdd(u + 3, acc.w);
}

// ---------------------------------------------------------------------------
// Kernel E: fusion_c += u_c @ Wv (bv pre-initialized by prep)
// grid: (C, 8 colsegs, 4 isegs), block: 128
// ---------------------------------------------------------------------------
__global__ void __launch_bounds__(128) fusion_kernel(const float* __restrict__ Wv,
                                                     float* __restrict__ out) {
    __shared__ float su[256];
    const int c  = blockIdx.x;
    const int t  = threadIdx.x;
    const int i0 = blockIdx.z * 256;
    su[t]       = g_u[c * DD + i0 + t];
    su[t + 128] = g_u[c * DD + i0 + t + 128];
    __syncthreads();

    const int j = blockIdx.y * 128 + t;
    float acc = 0.f;
    #pragma unroll 8
    for (int i = 0; i < 256; ++i) acc += su[i] * Wv[(size_t)(i0 + i) * DD + j];
    atomicAdd(&out[(size_t)CC * KK * DD + (size_t)c * DD + j], acc);
}

// ---------------------------------------------------------------------------
extern "C" void kernel_launch(void* const* d_in, const int* in_sizes, int n_in,
                              void* d_out, int out_size) {
    const float* feats = (const float*)d_in[0];  // [C, N, D]
    const float* keyf  = (const float*)d_in[1];  // [C, 1, D]
    const float* Wq    = (const float*)d_in[2];  // [D, DQ]
    const float* bq    = (const float*)d_in[3];  // [DQ]
    const float* Wv    = (const float*)d_in[4];  // [D, D]
    const float* bv    = (const float*)d_in[5];  // [D]
    float* out = (float*)d_out;                  // [C*K*D | C*D]

    prep_kernel<<<CC, 128>>>(keyf, Wq, bq, bv, out);
    score_kernel<<<dim3(256, CC), 256>>>(feats);
    select_kernel<<<CC, 1024>>>();
    gather_kernel<<<dim3(CC, 32), 256>>>(feats, out);
    fusion_kernel<<<dim3(CC, 8, 4), 128>>>(Wv, out);
}

// round 5
// speedup vs baseline: 2.9753x; 2.3125x over previous
#include <cuda_runtime.h>
#include <cuda_bf16.h>
#include <math.h>

#define CC   8
#define NN   16384
#define DD   1024
#define DQQ  128
#define KK   128
#define CAND_CAP 2048

static __device__ __align__(16) float g_w[CC * DD];
static __device__ float g_cc[CC];
static __device__ float g_scores[CC * NN];
static __device__ int   g_topidx[CC * KK];
static __device__ float g_weights[CC * KK];
static __device__ float g_u[CC * DD];
static __device__ float g_qk[CC * DQQ];
static __device__ unsigned int g_hist[CC * 2048];
static __device__ float g_esum[CC];

__device__ __forceinline__ unsigned int f2k(float f) {
    unsigned int u = __float_as_uint(f);
    return (u & 0x80000000u) ? ~u : (u | 0x80000000u);
}
__device__ __forceinline__ float k2f(unsigned int k) {
    unsigned int u = (k & 0x80000000u) ? (k & 0x7fffffffu) : ~k;
    return __uint_as_float(u);
}

// ---------------------------------------------------------------------------
// Kernel Z: zero scratch + init fusion output region to bv. grid 64 x 256
// ---------------------------------------------------------------------------
__global__ void zero_kernel(const float* __restrict__ bv, float* __restrict__ out) {
    const int idx = blockIdx.x * 256 + threadIdx.x;   // 0..16383
    g_hist[idx] = 0u;
    if (idx < CC * DD) {
        g_u[idx] = 0.f;
        out[(size_t)CC * KK * DD + idx] = bv[idx & (DD - 1)];
    }
    if (idx < CC * DQQ) g_qk[idx] = 0.f;
    if (idx < CC) g_esum[idx] = 0.f;
}

// ---------------------------------------------------------------------------
// Kernel A1: qk[c][j] = sum_i key[c][i] * Wq[i][j] + bq[j]  (via partials)
// grid (C, 8), block 128: block reduces a 128-row chunk of Wq.
// ---------------------------------------------------------------------------
__global__ void __launch_bounds__(128) qk_kernel(const float* __restrict__ key_feats,
                                                 const float* __restrict__ Wq,
                                                 const float* __restrict__ bq) {
    __shared__ float s_key[128];
    const int c  = blockIdx.x;
    const int ib = blockIdx.y * 128;
    const int j  = threadIdx.x;

    s_key[j] = key_feats[c * DD + ib + j];
    __syncthreads();

    float acc = (blockIdx.y == 0) ? bq[j] : 0.f;
    #pragma unroll 8
    for (int k = 0; k < 128; ++k)
        acc += s_key[k] * Wq[(size_t)(ib + k) * DQQ + j];
    atomicAdd(&g_qk[c * DQQ + j], acc);
}

// ---------------------------------------------------------------------------
// Kernel A2: w[c][i] = Wq[i] . qk[c]  (warp per row), cc = bq . qk
// grid (C, 8), block 128 (4 warps, 32 rows each)
// ---------------------------------------------------------------------------
__global__ void __launch_bounds__(128) w_kernel(const float* __restrict__ Wq,
                                                const float* __restrict__ bq) {
    __shared__ float s_qk[DQQ];
    const int c    = blockIdx.x;
    const int rb   = blockIdx.y * 128;
    const int t    = threadIdx.x;
    const int warp = t >> 5;
    const int lane = t & 31;

    s_qk[t] = g_qk[c * DQQ + t];
    __syncthreads();

    const float4 qk4 = reinterpret_cast<const float4*>(s_qk)[lane];

    if (blockIdx.y == 0 && warp == 0) {
        const float4 b4 = reinterpret_cast<const float4*>(bq)[lane];
        float cc = b4.x * qk4.x + b4.y * qk4.y + b4.z * qk4.z + b4.w * qk4.w;
        #pragma unroll
        for (int o = 16; o > 0; o >>= 1) cc += __shfl_xor_sync(0xffffffffu, cc, o);
        if (lane == 0) g_cc[c] = cc;
    }

    #pragma unroll 1
    for (int r = warp; r < 128; r += 4) {
        const int i = rb + r;
        const float4 w4 = reinterpret_cast<const float4*>(Wq + (size_t)i * DQQ)[lane];
        float acc = w4.x * qk4.x + w4.y * qk4.y + w4.z * qk4.z + w4.w * qk4.w;
        #pragma unroll
        for (int o = 16; o > 0; o >>= 1) acc += __shfl_xor_sync(0xffffffffu, acc, o);
        if (lane == 0) g_w[c * DD + i] = acc;
    }
}

// ---------------------------------------------------------------------------
// Kernel B: raw attention scores. Warp-per-row, streaming loads (__ldcs).
// THE 512MB kernel. grid (256, C), block 256. 64 patches/block, 8/warp.
// ---------------------------------------------------------------------------
__global__ void __launch_bounds__(256) score_kernel(const float* __restrict__ feats) {
    const int c    = blockIdx.y;
    const int warp = threadIdx.x >> 5;
    const int lane = threadIdx.x & 31;

    float4 wreg[8];
    const float4* w4 = reinterpret_cast<const float4*>(g_w + c * DD);
    #pragma unroll
    for (int j = 0; j < 8; ++j) wreg[j] = w4[j * 32 + lane];
    const float cc = g_cc[c];

    const int PPB  = 64;
    const int base = blockIdx.x * PPB;

    #pragma unroll 1
    for (int p = warp; p < PPB; p += 8) {
        const int n = base + p;
        const float4* row = reinterpret_cast<const float4*>(
            feats + ((size_t)c * NN + n) * DD);
        float4 f0 = __ldcs(&row[0 * 32 + lane]);
        float4 f1 = __ldcs(&row[1 * 32 + lane]);
        float4 f2 = __ldcs(&row[2 * 32 + lane]);
        float4 f3 = __ldcs(&row[3 * 32 + lane]);
        float4 f4 = __ldcs(&row[4 * 32 + lane]);
        float4 f5 = __ldcs(&row[5 * 32 + lane]);
        float4 f6 = __ldcs(&row[6 * 32 + lane]);
        float4 f7 = __ldcs(&row[7 * 32 + lane]);

        float acc = f0.x * wreg[0].x + f0.y * wreg[0].y + f0.z * wreg[0].z + f0.w * wreg[0].w;
        acc += f1.x * wreg[1].x + f1.y * wreg[1].y + f1.z * wreg[1].z + f1.w * wreg[1].w;
        acc += f2.x * wreg[2].x + f2.y * wreg[2].y + f2.z * wreg[2].z + f2.w * wreg[2].w;
        acc += f3.x * wreg[3].x + f3.y * wreg[3].y + f3.z * wreg[3].z + f3.w * wreg[3].w;
        acc += f4.x * wreg[4].x + f4.y * wreg[4].y + f4.z * wreg[4].z + f4.w * wreg[4].w;
        acc += f5.x * wreg[5].x + f5.y * wreg[5].y + f5.z * wreg[5].z + f5.w * wreg[5].w;
        acc += f6.x * wreg[6].x + f6.y * wreg[6].y + f6.z * wreg[6].z + f6.w * wreg[6].w;
        acc += f7.x * wreg[7].x + f7.y * wreg[7].y + f7.z * wreg[7].z + f7.w * wreg[7].w;

        #pragma unroll
        for (int o = 16; o > 0; o >>= 1)
            acc += __shfl_xor_sync(0xffffffffu, acc, o);
        if (lane == 0) g_scores[c * NN + n] = acc + cc;
    }
}

// ---------------------------------------------------------------------------
// Kernel H: parallel histogram + softmax denominator. grid (C, 16), block 256
// (scores are L2-resident; zero-reference exp safe: |s|/sqrt(128) < ~3)
// ---------------------------------------------------------------------------
__global__ void __launch_bounds__(256) hist_kernel() {
    __shared__ float s_part[8];
    const int c    = blockIdx.x;
    const int base = blockIdx.y * 1024;
    const int t    = threadIdx.x;
    const float invSqDQ = 0.08838834764831843f;

    float esum = 0.f;
    #pragma unroll
    for (int k = 0; k < 4; ++k) {
        float f = g_scores[c * NN + base + k * 256 + t];
        esum += expf(f * invSqDQ);
        atomicAdd(&g_hist[c * 2048 + (f2k(f) >> 21)], 1u);
    }
    #pragma unroll
    for (int o = 16; o > 0; o >>= 1) esum += __shfl_xor_sync(0xffffffffu, esum, o);
    if ((t & 31) == 0) s_part[t >> 5] = esum;
    __syncthreads();
    if (t == 0) {
        float s = 0.f;
        #pragma unroll
        for (int i = 0; i < 8; ++i) s += s_part[i];
        atomicAdd(&g_esum[c], s);
    }
}

// ---------------------------------------------------------------------------
// Kernel C: per-cluster top-K (sorted desc, stable ties) + both softmaxes.
// grid: (C), block: 1024
// ---------------------------------------------------------------------------
__device__ __forceinline__ float blk_sum_f32(float v, float* red) {
    int t = threadIdx.x;
    red[t] = v; __syncthreads();
    for (int s = 512; s > 0; s >>= 1) {
        if (t < s) red[t] += red[t + s];
        __syncthreads();
    }
    float r = red[0];
    __syncthreads();
    return r;
}
__device__ __forceinline__ int blk_max_i32(int v, int* red) {
    int t = threadIdx.x;
    red[t] = v; __syncthreads();
    for (int s = 512; s > 0; s >>= 1) {
        if (t < s) { int o = red[t + s]; if (o > red[t]) red[t] = o; }
        __syncthreads();
    }
    int r = red[0];
    __syncthreads();
    return r;
}

__global__ void __launch_bounds__(1024) select_kernel() {
    __shared__ unsigned int       hist[2048];
    __shared__ unsigned long long cand[CAND_CAP];
    __shared__ float              redf[1024];
    __shared__ int                redi[1024];
    __shared__ unsigned long long red64[1024];
    __shared__ unsigned int       s_cnt;
    __shared__ float              s_p0;
    __shared__ unsigned long long s_prev;

    const int c = blockIdx.x;
    const int t = threadIdx.x;
    const float invSqDQ = 0.08838834764831843f;  // 1/sqrt(128)
    const float invSqD  = 0.03125f;              // 1/sqrt(1024)

    hist[t]        = g_hist[c * 2048 + t];
    hist[t + 1024] = g_hist[c * 2048 + t + 1024];
    if (t == 0) s_cnt = 0u;
    __syncthreads();

    // Suffix scan: hist[b] <- count of keys in buckets >= b (Hillis-Steele)
    #pragma unroll
    for (int s = 1; s < 2048; s <<= 1) {
        unsigned int a0 = hist[t]        + ((t + s < 2048)        ? hist[t + s]        : 0u);
        unsigned int a1 = hist[t + 1024] + ((t + 1024 + s < 2048) ? hist[t + 1024 + s] : 0u);
        __syncthreads();
        hist[t] = a0; hist[t + 1024] = a1;
        __syncthreads();
    }

    // B = largest bucket with suffix count >= K
    int loc = -1;
    if (hist[t + 1024] >= KK) loc = t + 1024;
    else if (hist[t] >= KK)   loc = t;
    const int B = blk_max_i32(loc, redi);
    __syncthreads();

    // Collect candidates (L2-resident scores)
    for (int i = t; i < NN; i += 1024) {
        unsigned int key = f2k(g_scores[c * NN + i]);
        if ((int)(key >> 21) >= B) {
            unsigned int pos = atomicAdd(&s_cnt, 1u);
            if (pos < CAND_CAP)
                cand[pos] = ((unsigned long long)key << 14) |
                            (unsigned long long)(16383 - i);  // tie: lower idx wins
        }
    }
    __syncthreads();
    const unsigned int M = s_cnt;

    if (M <= CAND_CAP) {
        int P = 128;
        while (P < (int)M) P <<= 1;
        for (int i = (int)M + t; i < P; i += 1024) cand[i] = 0ull;
        __syncthreads();
        for (int k = 2; k <= P; k <<= 1) {
            for (int j = k >> 1; j > 0; j >>= 1) {
                for (int i = t; i < P; i += 1024) {
                    int ixj = i ^ j;
                    if (ixj > i) {
                        unsigned long long a = cand[i], b = cand[ixj];
                        bool swap_ = ((i & k) == 0) ? (a < b) : (a > b);
                        if (swap_) { cand[i] = b; cand[ixj] = a; }
                    }
                }
                __syncthreads();
            }
        }
    } else {
        // Degenerate-ties fallback: K sequential arg-maxes (exact; never hit on
        // continuous data)
        if (t == 0) s_prev = 0xFFFFFFFFFFFFFFFFull;
        __syncthreads();
        for (int kk = 0; kk < KK; ++kk) {
            unsigned long long prev = s_prev;
            unsigned long long local = 0ull;
            for (int i = t; i < NN; i += 1024) {
                unsigned int key = f2k(g_scores[c * NN + i]);
                unsigned long long v = ((unsigned long long)key << 14) |
                                       (unsigned long long)(16383 - i);
                if (v < prev && v > local) local = v;
            }
            red64[t] = local; __syncthreads();
            for (int s = 512; s > 0; s >>= 1) {
                if (t < s) { unsigned long long o = red64[t + s]; if (o > red64[t]) red64[t] = o; }
                __syncthreads();
            }
            if (t == 0) { cand[kk] = red64[0]; s_prev = red64[0]; }
            __syncthreads();
        }
    }

    // Top-128: first-softmax probs, then re-softmax over top-K
    float p = 0.f;
    if (t < KK) {
        unsigned long long v = cand[t];
        int idx = 16383 - (int)(v & 0x3FFFull);
        float f = k2f((unsigned int)(v >> 14));
        p = expf(f * invSqDQ) / g_esum[c];
        g_topidx[c * KK + t] = idx;
        if (t == 0) s_p0 = p;   // cand sorted desc -> t==0 is max prob
    }
    __syncthreads();
    float e = (t < KK) ? expf((p - s_p0) * invSqD) : 0.f;
    float wsum = blk_sum_f32(e, redf);
    if (t < KK) g_weights[c * KK + t] = e / wsum;
}

// ---------------------------------------------------------------------------
// Kernel D: gather selected rows to output + partial weighted sums into g_u.
// grid (C, 32), block 256 (thread = one float4 column; 4 rows per block)
// ---------------------------------------------------------------------------
__global__ void __launch_bounds__(256) gather_kernel(const float* __restrict__ feats,
                                                     float* __restrict__ out) {
    __shared__ float sw[4];
    __shared__ int   sidx[4];
    const int c  = blockIdx.x;
    const int ks = blockIdx.y * 4;
    const int t  = threadIdx.x;
    if (t < 4) {
        sw[t]   = g_weights[c * KK + ks + t];
        sidx[t] = g_topidx[c * KK + ks + t];
    }
    __syncthreads();

    float4 acc = make_float4(0.f, 0.f, 0.f, 0.f);
    #pragma unroll
    for (int r = 0; r < 4; ++r) {
        const float4* row = reinterpret_cast<const float4*>(
            feats + ((size_t)c * NN + sidx[r]) * DD);
        float4 v = row[t];
        reinterpret_cast<float4*>(out + ((size_t)(c * KK + ks + r)) * DD)[t] = v;
        float w = sw[r];
        acc.x += w * v.x; acc.y += w * v.y; acc.z += w * v.z; acc.w += w * v.w;
    }
    float* u = g_u + c * DD + t * 4;
    atomicAdd(u + 0, acc.x);
    atomicAdd(u + 1, acc.y);
    atomicAdd(u + 2, acc.z);
    atomicAdd(u + 3, acc.w);
}

// ---------------------------------------------------------------------------
// Kernel E: fusion_c += u_c @ Wv (bv pre-initialized by zero_kernel)
// grid (C, 8 colsegs, 4 isegs), block 128
// ---------------------------------------------------------------------------
__global__ void __launch_bounds__(128) fusion_kernel(const float* __restrict__ Wv,
                                                     float* __restrict__ out) {
    __shared__ float su[256];
    const int c  = blockIdx.x;
    const int t  = threadIdx.x;
    const int i0 = blockIdx.z * 256;
    su[t]       = g_u[c * DD + i0 + t];
    su[t + 128] = g_u[c * DD + i0 + t + 128];
    __syncthreads();

    const int j = blockIdx.y * 128 + t;
    float acc = 0.f;
    #pragma unroll 8
    for (int i = 0; i < 256; ++i) acc += su[i] * Wv[(size_t)(i0 + i) * DD + j];
    atomicAdd(&out[(size_t)CC * KK * DD + (size_t)c * DD + j], acc);
}

// ---------------------------------------------------------------------------
extern "C" void kernel_launch(void* const* d_in, const int* in_sizes, int n_in,
                              void* d_out, int out_size) {
    const float* feats = (const float*)d_in[0];  // [C, N, D]
    const float* keyf  = (const float*)d_in[1];  // [C, 1, D]
    const float* Wq    = (const float*)d_in[2];  // [D, DQ]
    const float* bq    = (const float*)d_in[3];  // [DQ]
    const float* Wv    = (const float*)d_in[4];  // [D, D]
    const float* bv    = (const float*)d_in[5];  // [D]
    float* out = (float*)d_out;                  // [C*K*D | C*D]

    zero_kernel<<<64, 256>>>(bv, out);
    qk_kernel<<<dim3(CC, 8), 128>>>(keyf, Wq, bq);
    w_kernel<<<dim3(CC, 8), 128>>>(Wq, bq);
    score_kernel<<<dim3(256, CC), 256>>>(feats);
    hist_kernel<<<dim3(CC, 16), 256>>>();
    select_kernel<<<CC, 1024>>>();
    gather_kernel<<<dim3(CC, 32), 256>>>(feats, out);
    fusion_kernel<<<dim3(CC, 8, 4), 128>>>(Wv, out);
}